// round 3
// baseline (speedup 1.0000x reference)
#include <cuda_runtime.h>
#include <cuda_bf16.h>
#include <cstdint>

// GCN 2-layer, N=500000, E=16000000 — dst-binned formulation.
//
//   deg_i = indeg(i) + 1;  dis_i = rsqrt(deg_i);  p_j = dis_j * x_j
//   s_i = dis_i * ( sum_{j->i} p_j + dis_i*x_i )
//   h_i[k] = relu(s_i*W1[k] + b1[k]);  q_i = dis_i * (h_i @ W2)
//   out_i = dis_i * ( sum_{j->i} q_j + q_i ) + b2
//
// Edges are binned by dst>>10 (1024-node slices). The binned layout is built
// once (CTA-local multisplit: smem histogram -> prefix -> global cursor
// reservation -> smem local sort -> coalesced flush) and reused by three
// per-bucket kernels that accumulate into SHARED MEMORY instead of global
// atomics. Only the per-edge src gather remains a random L2 transaction.
//
// Edge dtype (int32 vs int64) detected on device (JAX x64-disabled gives
// int32 despite the reference asking for int64).

static constexpr int N_MAX   = 500000;
static constexpr int SHIFT   = 10;
static constexpr int SLICE   = 1 << SHIFT;          // 1024 nodes / bucket
static constexpr int NBMAX   = 512;                 // >= ceil(500000/1024)=489
static constexpr int CAP     = 40960;               // mean 32768 + huge slack
static constexpr int BIN_T   = 256;                 // bin kernel threads
static constexpr int BIN_CHUNK = 4096;              // edges per bin CTA

__device__ int    g_is64;
__device__ int    g_cursor[NBMAX];                  // bucket fill counts
__device__ int2   g_binned[(size_t)NBMAX * CAP];    // (src, dst) sorted by bucket
__device__ float  g_dis[N_MAX];
__device__ float  g_p[N_MAX];                       // dis_j * x_j
__device__ float2 g_q[N_MAX];                       // dis_i * (h_i @ W2)

// ---------------------------------------------------------------- dtype probe
__global__ void k_detect(const long long* __restrict__ ei, int n_check, int N) {
    if (blockIdx.x == 0 && threadIdx.x == 0) {
        int ok = 1;
        for (int i = 0; i < n_check; i++) {
            long long v = ei[i];
            if (v < 0 || v >= (long long)N) { ok = 0; break; }
        }
        g_is64 = ok;
    }
}

// ---------------------------------------------------------------- cursor zero
__global__ void k_czero(int nb) {
    int i = blockIdx.x * blockDim.x + threadIdx.x;
    if (i < nb) g_cursor[i] = 0;
}

// ---------------------------------------------------------------- binning (multisplit)
__global__ void k_bin(const void* __restrict__ edge, int E, int nb) {
    __shared__ int2 stage[BIN_CHUNK];   // 32 KB
    __shared__ int  hist[NBMAX];
    __shared__ int  lbase[NBMAX];
    __shared__ int  gbase[NBMAX];
    __shared__ int  lcur[NBMAX];

    const int t = threadIdx.x;
    const long long base = (long long)blockIdx.x * BIN_CHUNK;
    int cnt = (int)min((long long)BIN_CHUNK, (long long)E - base);
    if (cnt <= 0) return;

    for (int i = t; i < nb; i += BIN_T) { hist[i] = 0; lcur[i] = 0; }
    __syncthreads();

    const bool is64 = (g_is64 != 0);

    // pass 1: histogram over dst
    if (is64) {
        const long long* dst = (const long long*)edge + E;
        for (int k = t; k < cnt; k += BIN_T)
            atomicAdd(&hist[((int)dst[base + k]) >> SHIFT], 1);
    } else {
        const int* dst = (const int*)edge + E;
        for (int k = t; k < cnt; k += BIN_T)
            atomicAdd(&hist[dst[base + k] >> SHIFT], 1);
    }
    __syncthreads();

    if (t == 0) {                       // exclusive prefix over <=512 buckets
        int acc = 0;
        for (int b = 0; b < nb; b++) { lbase[b] = acc; acc += hist[b]; }
    }
    __syncthreads();

    for (int b = t; b < nb; b += BIN_T)
        if (hist[b] > 0) gbase[b] = atomicAdd(&g_cursor[b], hist[b]);
    __syncthreads();

    // pass 2: re-read chunk, locally sort into smem by bucket
    if (is64) {
        const long long* src = (const long long*)edge;
        const long long* dst = src + E;
        for (int k = t; k < cnt; k += BIN_T) {
            int s = (int)src[base + k], d = (int)dst[base + k];
            int b = d >> SHIFT;
            int pos = lbase[b] + atomicAdd(&lcur[b], 1);
            stage[pos] = make_int2(s, d);
        }
    } else {
        const int* src = (const int*)edge;
        const int* dst = src + E;
        for (int k = t; k < cnt; k += BIN_T) {
            int s = src[base + k], d = dst[base + k];
            int b = d >> SHIFT;
            int pos = lbase[b] + atomicAdd(&lcur[b], 1);
            stage[pos] = make_int2(s, d);
        }
    }
    __syncthreads();

    // flush: consecutive j within a bucket segment -> consecutive global slots
    for (int j = t; j < cnt; j += BIN_T) {
        int2 e = stage[j];
        int  b = e.y >> SHIFT;
        long long gp = (long long)b * CAP + gbase[b] + (j - lbase[b]);
        g_binned[gp] = e;
    }
}

// ---------------------------------------------------------------- deg + dis + p (per bucket)
__global__ void k_degA(const float* __restrict__ x, int N) {
    __shared__ int cnt[SLICE];
    const int b = blockIdx.x, t = threadIdx.x, T = blockDim.x;
    for (int i = t; i < SLICE; i += T) cnt[i] = 0;
    __syncthreads();

    const int  ne = g_cursor[b];
    const int2* eb = g_binned + (size_t)b * CAP;

    int i = t;
    for (; i + 3 * T < ne; i += 4 * T) {
        int2 e0 = eb[i], e1 = eb[i + T], e2 = eb[i + 2 * T], e3 = eb[i + 3 * T];
        atomicAdd(&cnt[e0.y & (SLICE - 1)], 1);
        atomicAdd(&cnt[e1.y & (SLICE - 1)], 1);
        atomicAdd(&cnt[e2.y & (SLICE - 1)], 1);
        atomicAdd(&cnt[e3.y & (SLICE - 1)], 1);
    }
    for (; i < ne; i += T) atomicAdd(&cnt[eb[i].y & (SLICE - 1)], 1);
    __syncthreads();

    for (int l = t; l < SLICE; l += T) {
        int node = (b << SHIFT) + l;
        if (node < N) {
            float dis = rsqrtf((float)(cnt[l] + 1));   // +1 self loop
            g_dis[node] = dis;
            g_p[node]   = dis * x[node];
        }
    }
}

// ---------------------------------------------------------------- layer-1 scatter + MLP (per bucket)
__global__ void k_s1(const float* __restrict__ x,
                     const float* __restrict__ W1,
                     const float* __restrict__ b1,
                     const float* __restrict__ W2, int N) {
    __shared__ float tacc[SLICE];
    const int b = blockIdx.x, t = threadIdx.x, T = blockDim.x;
    for (int i = t; i < SLICE; i += T) tacc[i] = 0.0f;
    __syncthreads();

    const int  ne = g_cursor[b];
    const int2* eb = g_binned + (size_t)b * CAP;

    int i = t;
    for (; i + 3 * T < ne; i += 4 * T) {
        int2 e0 = eb[i], e1 = eb[i + T], e2 = eb[i + 2 * T], e3 = eb[i + 3 * T];
        float p0 = __ldg(&g_p[e0.x]);
        float p1 = __ldg(&g_p[e1.x]);
        float p2 = __ldg(&g_p[e2.x]);
        float p3 = __ldg(&g_p[e3.x]);
        atomicAdd(&tacc[e0.y & (SLICE - 1)], p0);
        atomicAdd(&tacc[e1.y & (SLICE - 1)], p1);
        atomicAdd(&tacc[e2.y & (SLICE - 1)], p2);
        atomicAdd(&tacc[e3.y & (SLICE - 1)], p3);
    }
    for (; i < ne; i += T) {
        int2 e = eb[i];
        atomicAdd(&tacc[e.y & (SLICE - 1)], __ldg(&g_p[e.x]));
    }
    __syncthreads();

    for (int l = t; l < SLICE; l += T) {
        int node = (b << SHIFT) + l;
        if (node < N) {
            float dis = g_dis[node];
            float s   = dis * (tacc[l] + dis * x[node]);
            float q0 = 0.0f, q1 = 0.0f;
#pragma unroll
            for (int k = 0; k < 8; k++) {
                float h = fmaxf(fmaf(s, __ldg(&W1[k]), __ldg(&b1[k])), 0.0f);
                q0 = fmaf(h, __ldg(&W2[2 * k + 0]), q0);
                q1 = fmaf(h, __ldg(&W2[2 * k + 1]), q1);
            }
            g_q[node] = make_float2(dis * q0, dis * q1);
        }
    }
}

// ---------------------------------------------------------------- layer-2 scatter + epilogue (per bucket)
__global__ void k_s2(const float* __restrict__ b2, float2* __restrict__ out, int N) {
    __shared__ float ux[SLICE];
    __shared__ float uy[SLICE];
    const int b = blockIdx.x, t = threadIdx.x, T = blockDim.x;
    for (int i = t; i < SLICE; i += T) { ux[i] = 0.0f; uy[i] = 0.0f; }
    __syncthreads();

    const int  ne = g_cursor[b];
    const int2* eb = g_binned + (size_t)b * CAP;

    int i = t;
    for (; i + 3 * T < ne; i += 4 * T) {
        int2 e0 = eb[i], e1 = eb[i + T], e2 = eb[i + 2 * T], e3 = eb[i + 3 * T];
        float2 q0 = __ldg(&g_q[e0.x]);
        float2 q1 = __ldg(&g_q[e1.x]);
        float2 q2 = __ldg(&g_q[e2.x]);
        float2 q3 = __ldg(&g_q[e3.x]);
        int l0 = e0.y & (SLICE - 1), l1 = e1.y & (SLICE - 1);
        int l2 = e2.y & (SLICE - 1), l3 = e3.y & (SLICE - 1);
        atomicAdd(&ux[l0], q0.x); atomicAdd(&uy[l0], q0.y);
        atomicAdd(&ux[l1], q1.x); atomicAdd(&uy[l1], q1.y);
        atomicAdd(&ux[l2], q2.x); atomicAdd(&uy[l2], q2.y);
        atomicAdd(&ux[l3], q3.x); atomicAdd(&uy[l3], q3.y);
    }
    for (; i < ne; i += T) {
        int2 e = eb[i];
        float2 q = __ldg(&g_q[e.x]);
        int l = e.y & (SLICE - 1);
        atomicAdd(&ux[l], q.x); atomicAdd(&uy[l], q.y);
    }
    __syncthreads();

    float b20 = __ldg(&b2[0]);
    float b21 = __ldg(&b2[1]);
    for (int l = t; l < SLICE; l += T) {
        int node = (b << SHIFT) + l;
        if (node < N) {
            float  dis = g_dis[node];
            float2 q   = g_q[node];
            out[node] = make_float2(fmaf(dis, ux[l] + q.x, b20),
                                    fmaf(dis, uy[l] + q.y, b21));
        }
    }
}

// ================================================================ launch
extern "C" void kernel_launch(void* const* d_in, const int* in_sizes, int n_in,
                              void* d_out, int out_size) {
    const float* x  = (const float*)d_in[0];
    const void*  ei = d_in[1];            // [2, E]: src then dst; int32 or int64
    const float* W1 = (const float*)d_in[2];
    const float* b1 = (const float*)d_in[3];
    const float* W2 = (const float*)d_in[4];
    const float* b2 = (const float*)d_in[5];

    const int N  = in_sizes[0];           // 500000
    const int E  = in_sizes[1] / 2;       // 16000000
    int nb = (N + SLICE - 1) >> SHIFT;    // 489
    if (nb > NBMAX) nb = NBMAX;

    const int nb_bin = (int)(((long long)E + BIN_CHUNK - 1) / BIN_CHUNK);

    k_detect<<<1, 32>>>((const long long*)ei, 64, N);
    k_czero <<<1, NBMAX>>>(nb);
    k_bin   <<<nb_bin, BIN_T>>>(ei, E, nb);
    k_degA  <<<nb, 256>>>(x, N);
    k_s1    <<<nb, 512>>>(x, W1, b1, W2, N);
    k_s2    <<<nb, 512>>>(b2, (float2*)d_out, N);
}

// round 4
// speedup vs baseline: 1.4259x; 1.4259x over previous
#include <cuda_runtime.h>
#include <cuda_bf16.h>
#include <cstdint>

// GCN 2-layer, N=500000, E=16000000 — packed dst-binned formulation, v2.
//
//   deg_i = indeg(i) + 1;  dis_i = rsqrt(deg_i);  p_j = dis_j * x_j
//   s_i = dis_i * ( sum_{j->i} p_j + dis_i*x_i )
//   h_i[k] = relu(s_i*W1[k] + b1[k]);  q_i = dis_i * (h_i @ W2)
//   out_i = dis_i * ( sum_{j->i} q_j + q_i ) + b2
//
// Edges binned by dst>>10 into 489 buckets, each edge packed into ONE int32:
//   bits [0:19)  src   (500000 < 2^19)
//   bits [19:29) dst & 1023
// Bin kernel is single-read (edges held in registers between histogram and
// placement), with a parallel block scan and coalesced staged flush.
// Per-bucket accumulation kernels run SPLIT=4 CTAs per bucket with private
// smem accumulators merged by coalesced global atomics.

static constexpr int N_MAX  = 500000;
static constexpr int SHIFT  = 10;
static constexpr int SLICE  = 1 << SHIFT;            // 1024
static constexpr int NBMAX  = 512;                   // >= 489 buckets
static constexpr int CAP    = 36864;                 // mean 32768 + ~22 sigma
static constexpr int BT     = 512;                   // bin threads
static constexpr int PER    = 12;                    // edges per bin thread
static constexpr int CHUNK  = BT * PER;              // 6144
static constexpr int SPLIT  = 4;                     // CTAs per bucket

__device__ int    g_is64;
__device__ int    g_cursor[NBMAX];
__device__ int    g_binned[(size_t)NBMAX * CAP];     // packed edges (64 MB)
__device__ int    g_cnt[N_MAX];                      // indegree
__device__ float  g_t[N_MAX];                        // layer-1 accumulator
__device__ float2 g_U[N_MAX];                        // layer-2 accumulator
__device__ float  g_dis[N_MAX];
__device__ float  g_p[N_MAX];                        // dis_j * x_j
__device__ float2 g_q[N_MAX];                        // dis_i * (h_i @ W2)

// ---------------------------------------------------------------- dtype probe
__global__ void k_detect(const long long* __restrict__ ei, int n_check, int N) {
    if (blockIdx.x == 0 && threadIdx.x == 0) {
        int ok = 1;
        for (int i = 0; i < n_check; i++) {
            long long v = ei[i];
            if (v < 0 || v >= (long long)N) { ok = 0; break; }
        }
        g_is64 = ok;
    }
}

// ---------------------------------------------------------------- zero state
__global__ void k_zero(int N) {
    int i = blockIdx.x * blockDim.x + threadIdx.x;
    if (i < N) {
        g_cnt[i] = 0;
        g_t[i]   = 0.0f;
        g_U[i]   = make_float2(0.0f, 0.0f);
    }
    if (i < NBMAX) g_cursor[i] = 0;
}

// ---------------------------------------------------------------- binning
__global__ __launch_bounds__(BT) void k_bin(const void* __restrict__ edge, int E) {
    __shared__ int            stage[CHUNK];   // 24 KB packed edges
    __shared__ unsigned short bktofs[CHUNK];  // 12 KB bucket id per slot
    __shared__ int            hist[NBMAX];    // becomes inclusive scan
    __shared__ int            lbase[NBMAX];
    __shared__ int            gbase[NBMAX];
    __shared__ int            lcur[NBMAX];

    const int t = threadIdx.x;
    const long long base = (long long)blockIdx.x * CHUNK;
    const int cnt = (int)min((long long)CHUNK, (long long)E - base);
    if (cnt <= 0) return;

    hist[t] = 0; lcur[t] = 0;
    __syncthreads();

    // load edges into registers, histogram buckets
    int pk[PER];
    int bb[PER];
    const bool is64 = (g_is64 != 0);
    if (is64) {
        const long long* src = (const long long*)edge;
        const long long* dst = src + E;
#pragma unroll
        for (int k = 0; k < PER; k++) {
            long long idx = base + k * BT + t;
            bb[k] = -1;
            if (idx < E) {
                int s = (int)__ldcs(&src[idx]);
                int d = (int)__ldcs(&dst[idx]);
                pk[k] = s | ((d & (SLICE - 1)) << 19);
                bb[k] = d >> SHIFT;
                atomicAdd(&hist[bb[k]], 1);
            }
        }
    } else {
        const int* src = (const int*)edge;
        const int* dst = src + E;
#pragma unroll
        for (int k = 0; k < PER; k++) {
            long long idx = base + k * BT + t;
            bb[k] = -1;
            if (idx < E) {
                int s = __ldcs(&src[idx]);
                int d = __ldcs(&dst[idx]);
                pk[k] = s | ((d & (SLICE - 1)) << 19);
                bb[k] = d >> SHIFT;
                atomicAdd(&hist[bb[k]], 1);
            }
        }
    }
    __syncthreads();

    // inclusive Hillis-Steele scan over 512 buckets (one element per thread)
    const int own = hist[t];
#pragma unroll
    for (int off = 1; off < NBMAX; off <<= 1) {
        int v = (t >= off) ? hist[t - off] : 0;
        __syncthreads();
        hist[t] += v;
        __syncthreads();
    }
    lbase[t] = hist[t] - own;

    // reserve global bucket ranges
    if (own > 0) gbase[t] = atomicAdd(&g_cursor[t], own);
    __syncthreads();

    // placement into smem stage, grouped by bucket
#pragma unroll
    for (int k = 0; k < PER; k++) {
        if (bb[k] >= 0) {
            int pos = lbase[bb[k]] + atomicAdd(&lcur[bb[k]], 1);
            stage[pos]  = pk[k];
            bktofs[pos] = (unsigned short)bb[k];
        }
    }
    __syncthreads();

    // coalesced flush (consecutive slots in a bucket -> consecutive global)
    for (int j = t; j < cnt; j += BT) {
        int b  = bktofs[j];
        int gb = gbase[b];
        long long gp = (long long)b * CAP + min(gb + (j - lbase[b]), CAP - 1);
        g_binned[gp] = stage[j];
    }
}

// ---------------------------------------------------------------- degree (split)
__global__ __launch_bounds__(512) void k_cnt(int nb) {
    __shared__ int cnt[SLICE];
    const int b    = blockIdx.x / SPLIT;
    const int part = blockIdx.x % SPLIT;
    const int t    = threadIdx.x;
    for (int i = t; i < SLICE; i += 512) cnt[i] = 0;
    __syncthreads();

    const int ne = min(g_cursor[b], CAP);
    const int s0 = (int)((long long)ne * part / SPLIT);
    const int s1 = (int)((long long)ne * (part + 1) / SPLIT);
    const int* eb = g_binned + (size_t)b * CAP;

    for (int i = s0 + t; i < s1; i += 512) {
        int pk = eb[i];
        atomicAdd(&cnt[(pk >> 19) & (SLICE - 1)], 1);
    }
    __syncthreads();

    const int nbase = b << SHIFT;
    for (int l = t; l < SLICE; l += 512)
        if (cnt[l]) atomicAdd(&g_cnt[nbase + l], cnt[l]);
}

// ---------------------------------------------------------------- node A: dis, p
__global__ void k_nodeA(const float* __restrict__ x, int N) {
    int i = blockIdx.x * blockDim.x + threadIdx.x;
    if (i < N) {
        float dis = rsqrtf((float)(g_cnt[i] + 1));   // +1 self loop
        g_dis[i] = dis;
        g_p[i]   = dis * x[i];
    }
}

// ---------------------------------------------------------------- layer-1 scatter (split)
__global__ __launch_bounds__(512) void k_s1(int nb) {
    __shared__ float acc[SLICE];
    const int b    = blockIdx.x / SPLIT;
    const int part = blockIdx.x % SPLIT;
    const int t    = threadIdx.x;
    for (int i = t; i < SLICE; i += 512) acc[i] = 0.0f;
    __syncthreads();

    const int ne = min(g_cursor[b], CAP);
    const int s0 = (int)((long long)ne * part / SPLIT);
    const int s1 = (int)((long long)ne * (part + 1) / SPLIT);
    const int* eb = g_binned + (size_t)b * CAP;

    int i = s0 + t;
    for (; i + 512 < s1; i += 1024) {
        int pk0 = eb[i], pk1 = eb[i + 512];
        float p0 = __ldg(&g_p[pk0 & 0x7FFFF]);
        float p1 = __ldg(&g_p[pk1 & 0x7FFFF]);
        atomicAdd(&acc[(pk0 >> 19) & (SLICE - 1)], p0);
        atomicAdd(&acc[(pk1 >> 19) & (SLICE - 1)], p1);
    }
    for (; i < s1; i += 512) {
        int pk = eb[i];
        atomicAdd(&acc[(pk >> 19) & (SLICE - 1)], __ldg(&g_p[pk & 0x7FFFF]));
    }
    __syncthreads();

    const int nbase = b << SHIFT;
    for (int l = t; l < SLICE; l += 512)
        if (acc[l] != 0.0f) atomicAdd(&g_t[nbase + l], acc[l]);
}

// ---------------------------------------------------------------- node B: MLP -> q
__global__ void k_nodeB(const float* __restrict__ x,
                        const float* __restrict__ W1,
                        const float* __restrict__ b1,
                        const float* __restrict__ W2, int N) {
    int i = blockIdx.x * blockDim.x + threadIdx.x;
    if (i >= N) return;
    float dis = g_dis[i];
    float s   = dis * (g_t[i] + dis * x[i]);
    float q0 = 0.0f, q1 = 0.0f;
#pragma unroll
    for (int k = 0; k < 8; k++) {
        float h = fmaxf(fmaf(s, __ldg(&W1[k]), __ldg(&b1[k])), 0.0f);
        q0 = fmaf(h, __ldg(&W2[2 * k + 0]), q0);
        q1 = fmaf(h, __ldg(&W2[2 * k + 1]), q1);
    }
    g_q[i] = make_float2(dis * q0, dis * q1);
}

// ---------------------------------------------------------------- layer-2 scatter (split)
__device__ __forceinline__ void red_add_v2(float2* addr, float a, float b) {
    asm volatile("red.global.add.v2.f32 [%0], {%1, %2};"
                 :: "l"(addr), "f"(a), "f"(b) : "memory");
}

__global__ __launch_bounds__(512) void k_s2(int nb) {
    __shared__ float ux[SLICE];
    __shared__ float uy[SLICE];
    const int b    = blockIdx.x / SPLIT;
    const int part = blockIdx.x % SPLIT;
    const int t    = threadIdx.x;
    for (int i = t; i < SLICE; i += 512) { ux[i] = 0.0f; uy[i] = 0.0f; }
    __syncthreads();

    const int ne = min(g_cursor[b], CAP);
    const int s0 = (int)((long long)ne * part / SPLIT);
    const int s1 = (int)((long long)ne * (part + 1) / SPLIT);
    const int* eb = g_binned + (size_t)b * CAP;

    int i = s0 + t;
    for (; i + 512 < s1; i += 1024) {
        int pk0 = eb[i], pk1 = eb[i + 512];
        float2 q0 = __ldg(&g_q[pk0 & 0x7FFFF]);
        float2 q1 = __ldg(&g_q[pk1 & 0x7FFFF]);
        int l0 = (pk0 >> 19) & (SLICE - 1);
        int l1 = (pk1 >> 19) & (SLICE - 1);
        atomicAdd(&ux[l0], q0.x); atomicAdd(&uy[l0], q0.y);
        atomicAdd(&ux[l1], q1.x); atomicAdd(&uy[l1], q1.y);
    }
    for (; i < s1; i += 512) {
        int pk = eb[i];
        float2 q = __ldg(&g_q[pk & 0x7FFFF]);
        int l = (pk >> 19) & (SLICE - 1);
        atomicAdd(&ux[l], q.x); atomicAdd(&uy[l], q.y);
    }
    __syncthreads();

    const int nbase = b << SHIFT;
    for (int l = t; l < SLICE; l += 512)
        if (ux[l] != 0.0f || uy[l] != 0.0f)
            red_add_v2(&g_U[nbase + l], ux[l], uy[l]);
}

// ---------------------------------------------------------------- epilogue
__global__ void k_final(const float* __restrict__ b2, float2* __restrict__ out, int N) {
    int i = blockIdx.x * blockDim.x + threadIdx.x;
    if (i >= N) return;
    float  dis = g_dis[i];
    float2 q   = g_q[i];
    float2 U   = g_U[i];
    out[i] = make_float2(fmaf(dis, U.x + q.x, __ldg(&b2[0])),
                         fmaf(dis, U.y + q.y, __ldg(&b2[1])));
}

// ================================================================ launch
extern "C" void kernel_launch(void* const* d_in, const int* in_sizes, int n_in,
                              void* d_out, int out_size) {
    const float* x  = (const float*)d_in[0];
    const void*  ei = d_in[1];            // [2, E]: src then dst; int32 or int64
    const float* W1 = (const float*)d_in[2];
    const float* b1 = (const float*)d_in[3];
    const float* W2 = (const float*)d_in[4];
    const float* b2 = (const float*)d_in[5];

    const int N  = in_sizes[0];           // 500000
    const int E  = in_sizes[1] / 2;       // 16000000
    int nb = (N + SLICE - 1) >> SHIFT;    // 489
    if (nb > NBMAX) nb = NBMAX;

    const int nb_bin  = (int)(((long long)E + CHUNK - 1) / CHUNK);
    const int nb_node = (N + 255) / 256;

    k_detect<<<1, 32>>>((const long long*)ei, 64, N);
    k_zero  <<<nb_node, 256>>>(N);
    k_bin   <<<nb_bin, BT>>>(ei, E);
    k_cnt   <<<nb * SPLIT, 512>>>(nb);
    k_nodeA <<<nb_node, 256>>>(x, N);
    k_s1    <<<nb * SPLIT, 512>>>(nb);
    k_nodeB <<<nb_node, 256>>>(x, W1, b1, W2, N);
    k_s2    <<<nb * SPLIT, 512>>>(nb);
    k_final <<<nb_node, 256>>>(b2, (float2*)d_out, N);
}

// round 5
// speedup vs baseline: 1.4333x; 1.0051x over previous
#include <cuda_runtime.h>
#include <cuda_bf16.h>
#include <cstdint>

// GCN 2-layer, N=500000, E=16000000 — packed dst-binned formulation, v3.
//
//   deg_i = indeg(i) + 1;  dis_i = rsqrt(deg_i);  p_j = dis_j * x_j
//   s_i = dis_i * ( sum_{j->i} p_j + dis_i*x_i )
//   h_i[k] = relu(s_i*W1[k] + b1[k]);  q_i = dis_i * (h_i @ W2)
//   out_i = dis_i * ( sum_{j->i} q_j + q_i ) + b2
//
// Edges binned by dst>>12 into 123 buckets (4096 nodes each); each edge packs
// into ONE int32: bits[0:19)=src, bits[19:31)=dst&4095. The bin kernel is
// single-read (edges in registers between histogram and placement), 128-entry
// block scan, uint8 bucket tags, coalesced staged flush with streaming stores.
// Consumers accumulate in smem (SPLIT=8 CTAs/bucket) and merge with coalesced
// global atomics. All big streams use __ldcs/__stcs so the L2-resident node
// arrays (g_p, g_q) stay hot for the random gathers.

static constexpr int N_MAX  = 500000;
static constexpr int SHIFT  = 12;
static constexpr int SLICE  = 1 << SHIFT;            // 4096
static constexpr int NB     = 128;                   // >= ceil(500000/4096)=123
static constexpr int CAP    = 139264;                // mean 130081 + ~25 sigma
static constexpr int BT     = 512;                   // bin threads
static constexpr int PER    = 16;                    // edges per bin thread
static constexpr int CHUNK  = BT * PER;              // 8192
static constexpr int SPLIT  = 8;                     // CTAs per bucket

__device__ int    g_is64;
__device__ int    g_cursor[NB];
__device__ int    g_binned[(size_t)NB * CAP];        // packed edges (~71 MB)
__device__ int    g_cnt[N_MAX];                      // indegree
__device__ float  g_t[N_MAX];                        // layer-1 accumulator
__device__ float2 g_U[N_MAX];                        // layer-2 accumulator
__device__ float  g_dis[N_MAX];
__device__ float  g_p[N_MAX];                        // dis_j * x_j
__device__ float2 g_q[N_MAX];                        // dis_i * (h_i @ W2)

// ---------------------------------------------------------------- dtype probe
__global__ void k_detect(const long long* __restrict__ ei, int n_check, int N) {
    if (blockIdx.x == 0 && threadIdx.x == 0) {
        int ok = 1;
        for (int i = 0; i < n_check; i++) {
            long long v = ei[i];
            if (v < 0 || v >= (long long)N) { ok = 0; break; }
        }
        g_is64 = ok;
    }
}

// ---------------------------------------------------------------- zero state
__global__ void k_zero(int N) {
    int i = blockIdx.x * blockDim.x + threadIdx.x;
    if (i < N) {
        g_cnt[i] = 0;
        g_t[i]   = 0.0f;
        g_U[i]   = make_float2(0.0f, 0.0f);
    }
    if (i < NB) g_cursor[i] = 0;
}

// ---------------------------------------------------------------- binning
__global__ __launch_bounds__(BT) void k_bin(const void* __restrict__ edge, int E) {
    __shared__ int           stage[CHUNK];    // 32 KB packed edges
    __shared__ unsigned char bkt[CHUNK];      // 8 KB bucket tag per slot
    __shared__ int           scan[NB];        // inclusive scan of hist
    __shared__ int           lbase[NB];
    __shared__ int           gbase[NB];
    __shared__ int           lcur[NB];

    const int t = threadIdx.x;
    const long long base = (long long)blockIdx.x * CHUNK;
    const int cnt = (int)min((long long)CHUNK, (long long)E - base);
    if (cnt <= 0) return;

    if (t < NB) { scan[t] = 0; lcur[t] = 0; }
    __syncthreads();

    // single read: edges into registers, histogram buckets
    int pk[PER];
    int bb[PER];
    const bool is64 = (g_is64 != 0);
    if (is64) {
        const long long* src = (const long long*)edge;
        const long long* dst = src + E;
#pragma unroll
        for (int k = 0; k < PER; k++) {
            long long idx = base + k * BT + t;
            bb[k] = -1;
            if (idx < E) {
                int s = (int)__ldcs(&src[idx]);
                int d = (int)__ldcs(&dst[idx]);
                pk[k] = s | ((d & (SLICE - 1)) << 19);
                bb[k] = d >> SHIFT;
                atomicAdd(&scan[bb[k]], 1);
            }
        }
    } else {
        const int* src = (const int*)edge;
        const int* dst = src + E;
#pragma unroll
        for (int k = 0; k < PER; k++) {
            long long idx = base + k * BT + t;
            bb[k] = -1;
            if (idx < E) {
                int s = __ldcs(&src[idx]);
                int d = __ldcs(&dst[idx]);
                pk[k] = s | ((d & (SLICE - 1)) << 19);
                bb[k] = d >> SHIFT;
                atomicAdd(&scan[bb[k]], 1);
            }
        }
    }
    __syncthreads();

    // inclusive Hillis-Steele scan over 128 buckets
    int own = 0;
    if (t < NB) own = scan[t];
#pragma unroll
    for (int off = 1; off < NB; off <<= 1) {
        int v = (t < NB && t >= off) ? scan[t - off] : 0;
        __syncthreads();
        if (t < NB) scan[t] += v;
        __syncthreads();
    }
    if (t < NB) {
        lbase[t] = scan[t] - own;
        if (own > 0) gbase[t] = atomicAdd(&g_cursor[t], own);
    }
    __syncthreads();

    // placement into smem stage, grouped by bucket
#pragma unroll
    for (int k = 0; k < PER; k++) {
        if (bb[k] >= 0) {
            int pos = lbase[bb[k]] + atomicAdd(&lcur[bb[k]], 1);
            stage[pos] = pk[k];
            bkt[pos]   = (unsigned char)bb[k];
        }
    }
    __syncthreads();

    // coalesced flush: consecutive slots in a bucket -> consecutive global
    for (int j = t; j < cnt; j += BT) {
        int b  = bkt[j];
        long long gp = (long long)b * CAP + min(gbase[b] + (j - lbase[b]), CAP - 1);
        __stcs(&g_binned[gp], stage[j]);
    }
}

// ---------------------------------------------------------------- degree (split)
__global__ __launch_bounds__(512) void k_cnt(int nb) {
    __shared__ int cnt[SLICE];
    const int b    = blockIdx.x / SPLIT;
    const int part = blockIdx.x % SPLIT;
    const int t    = threadIdx.x;
    for (int i = t; i < SLICE; i += 512) cnt[i] = 0;
    __syncthreads();

    const int ne = min(g_cursor[b], CAP);
    const int s0 = (int)((long long)ne * part / SPLIT);
    const int s1 = (int)((long long)ne * (part + 1) / SPLIT);
    const int* eb = g_binned + (size_t)b * CAP;

    for (int i = s0 + t; i < s1; i += 512) {
        int pk = __ldcs(&eb[i]);
        atomicAdd(&cnt[(pk >> 19) & (SLICE - 1)], 1);
    }
    __syncthreads();

    const int nbase = b << SHIFT;
    for (int l = t; l < SLICE; l += 512)
        if (cnt[l]) atomicAdd(&g_cnt[nbase + l], cnt[l]);
}

// ---------------------------------------------------------------- node A: dis, p
__global__ void k_nodeA(const float* __restrict__ x, int N) {
    int i = blockIdx.x * blockDim.x + threadIdx.x;
    if (i < N) {
        float dis = rsqrtf((float)(g_cnt[i] + 1));   // +1 self loop
        g_dis[i] = dis;
        g_p[i]   = dis * x[i];
    }
}

// ---------------------------------------------------------------- layer-1 scatter (split)
__global__ __launch_bounds__(512) void k_s1(int nb) {
    __shared__ float acc[SLICE];
    const int b    = blockIdx.x / SPLIT;
    const int part = blockIdx.x % SPLIT;
    const int t    = threadIdx.x;
    for (int i = t; i < SLICE; i += 512) acc[i] = 0.0f;
    __syncthreads();

    const int ne = min(g_cursor[b], CAP);
    const int s0 = (int)((long long)ne * part / SPLIT);
    const int s1 = (int)((long long)ne * (part + 1) / SPLIT);
    const int* eb = g_binned + (size_t)b * CAP;

    int i = s0 + t;
    for (; i + 512 < s1; i += 1024) {
        int pk0 = __ldcs(&eb[i]);
        int pk1 = __ldcs(&eb[i + 512]);
        float p0 = __ldg(&g_p[pk0 & 0x7FFFF]);
        float p1 = __ldg(&g_p[pk1 & 0x7FFFF]);
        atomicAdd(&acc[(pk0 >> 19) & (SLICE - 1)], p0);
        atomicAdd(&acc[(pk1 >> 19) & (SLICE - 1)], p1);
    }
    for (; i < s1; i += 512) {
        int pk = __ldcs(&eb[i]);
        atomicAdd(&acc[(pk >> 19) & (SLICE - 1)], __ldg(&g_p[pk & 0x7FFFF]));
    }
    __syncthreads();

    const int nbase = b << SHIFT;
    for (int l = t; l < SLICE; l += 512)
        if (acc[l] != 0.0f) atomicAdd(&g_t[nbase + l], acc[l]);
}

// ---------------------------------------------------------------- node B: MLP -> q
__global__ void k_nodeB(const float* __restrict__ x,
                        const float* __restrict__ W1,
                        const float* __restrict__ b1,
                        const float* __restrict__ W2, int N) {
    int i = blockIdx.x * blockDim.x + threadIdx.x;
    if (i >= N) return;
    float dis = g_dis[i];
    float s   = dis * (g_t[i] + dis * x[i]);
    float q0 = 0.0f, q1 = 0.0f;
#pragma unroll
    for (int k = 0; k < 8; k++) {
        float h = fmaxf(fmaf(s, __ldg(&W1[k]), __ldg(&b1[k])), 0.0f);
        q0 = fmaf(h, __ldg(&W2[2 * k + 0]), q0);
        q1 = fmaf(h, __ldg(&W2[2 * k + 1]), q1);
    }
    g_q[i] = make_float2(dis * q0, dis * q1);
}

// ---------------------------------------------------------------- layer-2 scatter (split)
__device__ __forceinline__ void red_add_v2(float2* addr, float a, float b) {
    asm volatile("red.global.add.v2.f32 [%0], {%1, %2};"
                 :: "l"(addr), "f"(a), "f"(b) : "memory");
}

__global__ __launch_bounds__(512) void k_s2(int nb) {
    __shared__ float ux[SLICE];
    __shared__ float uy[SLICE];
    const int b    = blockIdx.x / SPLIT;
    const int part = blockIdx.x % SPLIT;
    const int t    = threadIdx.x;
    for (int i = t; i < SLICE; i += 512) { ux[i] = 0.0f; uy[i] = 0.0f; }
    __syncthreads();

    const int ne = min(g_cursor[b], CAP);
    const int s0 = (int)((long long)ne * part / SPLIT);
    const int s1 = (int)((long long)ne * (part + 1) / SPLIT);
    const int* eb = g_binned + (size_t)b * CAP;

    int i = s0 + t;
    for (; i + 512 < s1; i += 1024) {
        int pk0 = __ldcs(&eb[i]);
        int pk1 = __ldcs(&eb[i + 512]);
        float2 q0 = __ldg(&g_q[pk0 & 0x7FFFF]);
        float2 q1 = __ldg(&g_q[pk1 & 0x7FFFF]);
        int l0 = (pk0 >> 19) & (SLICE - 1);
        int l1 = (pk1 >> 19) & (SLICE - 1);
        atomicAdd(&ux[l0], q0.x); atomicAdd(&uy[l0], q0.y);
        atomicAdd(&ux[l1], q1.x); atomicAdd(&uy[l1], q1.y);
    }
    for (; i < s1; i += 512) {
        int pk = __ldcs(&eb[i]);
        float2 q = __ldg(&g_q[pk & 0x7FFFF]);
        int l = (pk >> 19) & (SLICE - 1);
        atomicAdd(&ux[l], q.x); atomicAdd(&uy[l], q.y);
    }
    __syncthreads();

    const int nbase = b << SHIFT;
    for (int l = t; l < SLICE; l += 512)
        if (ux[l] != 0.0f || uy[l] != 0.0f)
            red_add_v2(&g_U[nbase + l], ux[l], uy[l]);
}

// ---------------------------------------------------------------- epilogue
__global__ void k_final(const float* __restrict__ b2, float2* __restrict__ out, int N) {
    int i = blockIdx.x * blockDim.x + threadIdx.x;
    if (i >= N) return;
    float  dis = g_dis[i];
    float2 q   = g_q[i];
    float2 U   = g_U[i];
    out[i] = make_float2(fmaf(dis, U.x + q.x, __ldg(&b2[0])),
                         fmaf(dis, U.y + q.y, __ldg(&b2[1])));
}

// ================================================================ launch
extern "C" void kernel_launch(void* const* d_in, const int* in_sizes, int n_in,
                              void* d_out, int out_size) {
    const float* x  = (const float*)d_in[0];
    const void*  ei = d_in[1];            // [2, E]: src then dst; int32 or int64
    const float* W1 = (const float*)d_in[2];
    const float* b1 = (const float*)d_in[3];
    const float* W2 = (const float*)d_in[4];
    const float* b2 = (const float*)d_in[5];

    const int N  = in_sizes[0];           // 500000
    const int E  = in_sizes[1] / 2;       // 16000000
    int nb = (N + SLICE - 1) >> SHIFT;    // 123
    if (nb > NB) nb = NB;

    const int nb_bin  = (int)(((long long)E + CHUNK - 1) / CHUNK);
    const int nb_node = (N + 255) / 256;

    k_detect<<<1, 32>>>((const long long*)ei, 64, N);
    k_zero  <<<nb_node, 256>>>(N);
    k_bin   <<<nb_bin, BT>>>(ei, E);
    k_cnt   <<<nb * SPLIT, 512>>>(nb);
    k_nodeA <<<nb_node, 256>>>(x, N);
    k_s1    <<<nb * SPLIT, 512>>>(nb);
    k_nodeB <<<nb_node, 256>>>(x, W1, b1, W2, N);
    k_s2    <<<nb * SPLIT, 512>>>(nb);
    k_final <<<nb_node, 256>>>(b2, (float2*)d_out, N);
}

// round 6
// speedup vs baseline: 1.4745x; 1.0288x over previous
#include <cuda_runtime.h>
#include <cuda_bf16.h>
#include <cstdint>

// GCN 2-layer, N=500000, E=16000000 — packed dst-binned formulation, v4.
//
//   deg_i = indeg(i) + 1;  dis_i = rsqrt(deg_i);  p_j = dis_j * x_j
//   s_i = dis_i * ( sum_{j->i} p_j + dis_i*x_i )
//   h_i[k] = relu(s_i*W1[k] + b1[k]);  q_i = dis_i * (h_i @ W2)
//   out_i = dis_i * ( sum_{j->i} q_j + q_i ) + b2
//
// Edges binned by dst>>12 into 123 buckets (4096 nodes each); each edge packs
// into ONE int32: bits[0:19)=src, bits[19:31)=dst&4095.
// Bin kernel v4: NO histogram/scan — per-bucket pre-partitioned smem regions,
// ONE smem atomic per edge, then per-bucket coalesced flush with one global
// cursor reservation per (CTA,bucket). Consumers accumulate in smem
// (SPLIT CTAs per bucket, batch-4 ILP) and merge with coalesced atomics.

static constexpr int N_MAX   = 500000;
static constexpr int SHIFT   = 12;
static constexpr int SLICE   = 1 << SHIFT;           // 4096
static constexpr int NB      = 128;                  // >= ceil(500000/4096)=123
static constexpr int CAP     = 139264;               // mean 130081 + ~25 sigma
static constexpr int BT      = 512;                  // bin threads
static constexpr int PER     = 8;                    // edges per bin thread
static constexpr int CHUNK   = BT * PER;             // 4096
static constexpr int REG_CAP = 80;                   // mean 32/bucket + 8.4 sigma
static constexpr int SPLIT   = 8;                    // CTAs per bucket

__device__ int    g_is64;
__device__ int    g_cursor[NB];
__device__ int    g_binned[(size_t)NB * CAP];        // packed edges (~71 MB)
__device__ int    g_cnt[N_MAX];                      // indegree
__device__ float  g_t[N_MAX];                        // layer-1 accumulator
__device__ float2 g_U[N_MAX];                        // layer-2 accumulator
__device__ float  g_dis[N_MAX];
__device__ float  g_p[N_MAX];                        // dis_j * x_j
__device__ float2 g_q[N_MAX];                        // dis_i * (h_i @ W2)

// ---------------------------------------------------------------- dtype probe
__global__ void k_detect(const long long* __restrict__ ei, int n_check, int N) {
    if (blockIdx.x == 0 && threadIdx.x == 0) {
        int ok = 1;
        for (int i = 0; i < n_check; i++) {
            long long v = ei[i];
            if (v < 0 || v >= (long long)N) { ok = 0; break; }
        }
        g_is64 = ok;
    }
}

// ---------------------------------------------------------------- zero state
__global__ void k_zero(int N) {
    int i = blockIdx.x * blockDim.x + threadIdx.x;
    if (i < N) {
        g_cnt[i] = 0;
        g_t[i]   = 0.0f;
        g_U[i]   = make_float2(0.0f, 0.0f);
    }
    if (i < NB) g_cursor[i] = 0;
}

// ---------------------------------------------------------------- binning v4
__global__ __launch_bounds__(BT) void k_bin(const void* __restrict__ edge, int E) {
    __shared__ int region[NB * REG_CAP];   // 40 KB: per-bucket slots
    __shared__ int lcur[NB];
    __shared__ int gbase[NB];

    const int t = threadIdx.x;
    const long long base = (long long)blockIdx.x * CHUNK;
    if (base >= E) return;

    if (t < NB) lcur[t] = 0;
    __syncthreads();

    // single pass: load, pack, place (one smem atomic per edge)
    const bool is64 = (g_is64 != 0);
    if (is64) {
        const long long* src = (const long long*)edge;
        const long long* dst = src + E;
#pragma unroll
        for (int k = 0; k < PER; k++) {
            long long idx = base + k * BT + t;
            if (idx < E) {
                int s = (int)__ldcs(&src[idx]);
                int d = (int)__ldcs(&dst[idx]);
                int b = d >> SHIFT;
                int pos = atomicAdd(&lcur[b], 1);
                if (pos < REG_CAP)
                    region[b * REG_CAP + pos] = s | ((d & (SLICE - 1)) << 19);
            }
        }
    } else {
        const int* src = (const int*)edge;
        const int* dst = src + E;
#pragma unroll
        for (int k = 0; k < PER; k++) {
            long long idx = base + k * BT + t;
            if (idx < E) {
                int s = __ldcs(&src[idx]);
                int d = __ldcs(&dst[idx]);
                int b = d >> SHIFT;
                int pos = atomicAdd(&lcur[b], 1);
                if (pos < REG_CAP)
                    region[b * REG_CAP + pos] = s | ((d & (SLICE - 1)) << 19);
            }
        }
    }
    __syncthreads();

    // reserve global ranges (one atomic per bucket per CTA)
    if (t < NB) {
        int c = min(lcur[t], REG_CAP);
        lcur[t]  = c;
        gbase[t] = (c > 0) ? atomicAdd(&g_cursor[t], c) : 0;
    }
    __syncthreads();

    // coalesced flush: warp per bucket (16 warps cover 128 buckets in 8 rounds)
    const int w = t >> 5, lane = t & 31;
    for (int b = w; b < NB; b += 16) {
        const int c  = lcur[b];
        const int gb = gbase[b];
        const long long gp0 = (long long)b * CAP;
        for (int j = lane; j < c; j += 32)
            __stcs(&g_binned[gp0 + min(gb + j, CAP - 1)], region[b * REG_CAP + j]);
    }
}

// ---------------------------------------------------------------- degree (split, batch-4)
__global__ __launch_bounds__(512) void k_cnt(int nb) {
    __shared__ int cnt[SLICE];
    const int b    = blockIdx.x / SPLIT;
    const int part = blockIdx.x % SPLIT;
    const int t    = threadIdx.x;
    for (int i = t; i < SLICE; i += 512) cnt[i] = 0;
    __syncthreads();

    const int ne = min(g_cursor[b], CAP);
    const int s0 = (int)((long long)ne * part / SPLIT);
    const int s1 = (int)((long long)ne * (part + 1) / SPLIT);
    const int* eb = g_binned + (size_t)b * CAP;

    int i = s0 + t;
    for (; i + 3 * 512 < s1; i += 4 * 512) {
        int pk0 = __ldcs(&eb[i]);
        int pk1 = __ldcs(&eb[i + 512]);
        int pk2 = __ldcs(&eb[i + 1024]);
        int pk3 = __ldcs(&eb[i + 1536]);
        atomicAdd(&cnt[(pk0 >> 19) & (SLICE - 1)], 1);
        atomicAdd(&cnt[(pk1 >> 19) & (SLICE - 1)], 1);
        atomicAdd(&cnt[(pk2 >> 19) & (SLICE - 1)], 1);
        atomicAdd(&cnt[(pk3 >> 19) & (SLICE - 1)], 1);
    }
    for (; i < s1; i += 512)
        atomicAdd(&cnt[(__ldcs(&eb[i]) >> 19) & (SLICE - 1)], 1);
    __syncthreads();

    const int nbase = b << SHIFT;
    for (int l = t; l < SLICE; l += 512)
        if (cnt[l]) atomicAdd(&g_cnt[nbase + l], cnt[l]);
}

// ---------------------------------------------------------------- node A: dis, p
__global__ void k_nodeA(const float* __restrict__ x, int N) {
    int i = blockIdx.x * blockDim.x + threadIdx.x;
    if (i < N) {
        float dis = rsqrtf((float)(g_cnt[i] + 1));   // +1 self loop
        g_dis[i] = dis;
        g_p[i]   = dis * x[i];
    }
}

// ---------------------------------------------------------------- layer-1 scatter (split, batch-4)
__global__ __launch_bounds__(512) void k_s1(int nb) {
    __shared__ float acc[SLICE];
    const int b    = blockIdx.x / SPLIT;
    const int part = blockIdx.x % SPLIT;
    const int t    = threadIdx.x;
    for (int i = t; i < SLICE; i += 512) acc[i] = 0.0f;
    __syncthreads();

    const int ne = min(g_cursor[b], CAP);
    const int s0 = (int)((long long)ne * part / SPLIT);
    const int s1 = (int)((long long)ne * (part + 1) / SPLIT);
    const int* eb = g_binned + (size_t)b * CAP;

    int i = s0 + t;
    for (; i + 3 * 512 < s1; i += 4 * 512) {
        int pk0 = __ldcs(&eb[i]);
        int pk1 = __ldcs(&eb[i + 512]);
        int pk2 = __ldcs(&eb[i + 1024]);
        int pk3 = __ldcs(&eb[i + 1536]);
        float p0 = __ldg(&g_p[pk0 & 0x7FFFF]);
        float p1 = __ldg(&g_p[pk1 & 0x7FFFF]);
        float p2 = __ldg(&g_p[pk2 & 0x7FFFF]);
        float p3 = __ldg(&g_p[pk3 & 0x7FFFF]);
        atomicAdd(&acc[(pk0 >> 19) & (SLICE - 1)], p0);
        atomicAdd(&acc[(pk1 >> 19) & (SLICE - 1)], p1);
        atomicAdd(&acc[(pk2 >> 19) & (SLICE - 1)], p2);
        atomicAdd(&acc[(pk3 >> 19) & (SLICE - 1)], p3);
    }
    for (; i < s1; i += 512) {
        int pk = __ldcs(&eb[i]);
        atomicAdd(&acc[(pk >> 19) & (SLICE - 1)], __ldg(&g_p[pk & 0x7FFFF]));
    }
    __syncthreads();

    const int nbase = b << SHIFT;
    for (int l = t; l < SLICE; l += 512)
        if (acc[l] != 0.0f) atomicAdd(&g_t[nbase + l], acc[l]);
}

// ---------------------------------------------------------------- node B: MLP -> q
__global__ void k_nodeB(const float* __restrict__ x,
                        const float* __restrict__ W1,
                        const float* __restrict__ b1,
                        const float* __restrict__ W2, int N) {
    int i = blockIdx.x * blockDim.x + threadIdx.x;
    if (i >= N) return;
    float dis = g_dis[i];
    float s   = dis * (g_t[i] + dis * x[i]);
    float q0 = 0.0f, q1 = 0.0f;
#pragma unroll
    for (int k = 0; k < 8; k++) {
        float h = fmaxf(fmaf(s, __ldg(&W1[k]), __ldg(&b1[k])), 0.0f);
        q0 = fmaf(h, __ldg(&W2[2 * k + 0]), q0);
        q1 = fmaf(h, __ldg(&W2[2 * k + 1]), q1);
    }
    g_q[i] = make_float2(dis * q0, dis * q1);
}

// ---------------------------------------------------------------- layer-2 scatter (split, batch-4)
__device__ __forceinline__ void red_add_v2(float2* addr, float a, float b) {
    asm volatile("red.global.add.v2.f32 [%0], {%1, %2};"
                 :: "l"(addr), "f"(a), "f"(b) : "memory");
}

__global__ __launch_bounds__(512) void k_s2(int nb) {
    __shared__ float ux[SLICE];
    __shared__ float uy[SLICE];
    const int b    = blockIdx.x / SPLIT;
    const int part = blockIdx.x % SPLIT;
    const int t    = threadIdx.x;
    for (int i = t; i < SLICE; i += 512) { ux[i] = 0.0f; uy[i] = 0.0f; }
    __syncthreads();

    const int ne = min(g_cursor[b], CAP);
    const int s0 = (int)((long long)ne * part / SPLIT);
    const int s1 = (int)((long long)ne * (part + 1) / SPLIT);
    const int* eb = g_binned + (size_t)b * CAP;

    int i = s0 + t;
    for (; i + 3 * 512 < s1; i += 4 * 512) {
        int pk0 = __ldcs(&eb[i]);
        int pk1 = __ldcs(&eb[i + 512]);
        int pk2 = __ldcs(&eb[i + 1024]);
        int pk3 = __ldcs(&eb[i + 1536]);
        float2 q0 = __ldg(&g_q[pk0 & 0x7FFFF]);
        float2 q1 = __ldg(&g_q[pk1 & 0x7FFFF]);
        float2 q2 = __ldg(&g_q[pk2 & 0x7FFFF]);
        float2 q3 = __ldg(&g_q[pk3 & 0x7FFFF]);
        int l0 = (pk0 >> 19) & (SLICE - 1), l1 = (pk1 >> 19) & (SLICE - 1);
        int l2 = (pk2 >> 19) & (SLICE - 1), l3 = (pk3 >> 19) & (SLICE - 1);
        atomicAdd(&ux[l0], q0.x); atomicAdd(&uy[l0], q0.y);
        atomicAdd(&ux[l1], q1.x); atomicAdd(&uy[l1], q1.y);
        atomicAdd(&ux[l2], q2.x); atomicAdd(&uy[l2], q2.y);
        atomicAdd(&ux[l3], q3.x); atomicAdd(&uy[l3], q3.y);
    }
    for (; i < s1; i += 512) {
        int pk = __ldcs(&eb[i]);
        float2 q = __ldg(&g_q[pk & 0x7FFFF]);
        int l = (pk >> 19) & (SLICE - 1);
        atomicAdd(&ux[l], q.x); atomicAdd(&uy[l], q.y);
    }
    __syncthreads();

    const int nbase = b << SHIFT;
    for (int l = t; l < SLICE; l += 512)
        if (ux[l] != 0.0f || uy[l] != 0.0f)
            red_add_v2(&g_U[nbase + l], ux[l], uy[l]);
}

// ---------------------------------------------------------------- epilogue
__global__ void k_final(const float* __restrict__ b2, float2* __restrict__ out, int N) {
    int i = blockIdx.x * blockDim.x + threadIdx.x;
    if (i >= N) return;
    float  dis = g_dis[i];
    float2 q   = g_q[i];
    float2 U   = g_U[i];
    out[i] = make_float2(fmaf(dis, U.x + q.x, __ldg(&b2[0])),
                         fmaf(dis, U.y + q.y, __ldg(&b2[1])));
}

// ================================================================ launch
extern "C" void kernel_launch(void* const* d_in, const int* in_sizes, int n_in,
                              void* d_out, int out_size) {
    const float* x  = (const float*)d_in[0];
    const void*  ei = d_in[1];            // [2, E]: src then dst; int32 or int64
    const float* W1 = (const float*)d_in[2];
    const float* b1 = (const float*)d_in[3];
    const float* W2 = (const float*)d_in[4];
    const float* b2 = (const float*)d_in[5];

    const int N  = in_sizes[0];           // 500000
    const int E  = in_sizes[1] / 2;       // 16000000
    int nb = (N + SLICE - 1) >> SHIFT;    // 123
    if (nb > NB) nb = NB;

    const int nb_bin  = (int)(((long long)E + CHUNK - 1) / CHUNK);
    const int nb_node = (N + 255) / 256;

    k_detect<<<1, 32>>>((const long long*)ei, 64, N);
    k_zero  <<<nb_node, 256>>>(N);
    k_bin   <<<nb_bin, BT>>>(ei, E);
    k_cnt   <<<nb * SPLIT, 512>>>(nb);
    k_nodeA <<<nb_node, 256>>>(x, N);
    k_s1    <<<nb * SPLIT, 512>>>(nb);
    k_nodeB <<<nb_node, 256>>>(x, W1, b1, W2, N);
    k_s2    <<<nb * SPLIT, 512>>>(nb);
    k_final <<<nb_node, 256>>>(b2, (float2*)d_out, N);
}